// round 4
// baseline (speedup 1.0000x reference)
#include <cuda_runtime.h>
#include <math.h>

#define Bsz 128
#define Nn  64
#define OBS 128
#define ACTD 32
#define OA  160
#define Dd  64

typedef unsigned long long u64;

// -------- scratch (no runtime alloc allowed) --------
__device__ float g_oape_act[Bsz*Nn*Dd];
__device__ float g_oape_pol[Bsz*Nn*Dd];
__device__ float g_av_delta[Bsz*Nn*Dd];
__device__ float g_S[Bsz*Nn*Dd];
__device__ float g_c1[Bsz*Nn*Dd];
__device__ float g_w[Bsz*Nn*Nn];

// Branch-free erf (Abramowitz-Stegun 7.1.26, max abs err 1.5e-7) -> exact-enough GELU.
__device__ __forceinline__ float gelu_f(float x) {
    float z = x * 0.70710678118654752440f;
    float a = fabsf(z);
    float t = __fdividef(1.0f, fmaf(0.3275911f, a, 1.0f));
    float p = fmaf(t, 1.061405429f, -1.453152027f);
    p = fmaf(t, p, 1.421413741f);
    p = fmaf(t, p, -0.284496736f);
    p = fmaf(t, p, 0.254829592f);
    p = p * t;
    float e = 1.0f - p * __expf(-a * a);
    float erfv = copysignf(e, z);
    return 0.5f * x * (1.0f + erfv);
}

// ---- packed f32x2 helpers (sm_103a; FFMA2 only reachable via PTX) ----
__device__ __forceinline__ u64 dup2(float v) {
    u64 r; asm("mov.b64 %0, {%1, %1};" : "=l"(r) : "f"(v)); return r;
}
__device__ __forceinline__ void fma2(u64 &d, u64 a, u64 b) {
    asm("fma.rn.f32x2 %0, %1, %2, %3;" : "=l"(d) : "l"(a), "l"(b), "l"(d));
}
__device__ __forceinline__ void unpk(float &lo, float &hi, u64 v) {
    asm("mov.b64 {%0, %1}, %2;" : "=f"(lo), "=f"(hi) : "l"(v));
}

// Accumulate a 4x4 microtile with f32x2 pairs along columns:
// acc[r][0] = (c0+0,c0+1), acc[r][1] = (c0+2,c0+3).
// X row-major stride ld (floats, ld%4==0, base 16B-aligned); Wp = W + c0, stride 64.
// Weight pairs come straight from the LDS.128 register quad (free reinterpret).
__device__ __forceinline__ void gemm_acc(u64 acc[4][2],
    const float* __restrict__ X, int ld, int Kc,
    const float* __restrict__ Wp, int r0)
{
    #pragma unroll 4
    for (int k = 0; k < Kc; k += 4) {
        float xv[4][4];
        #pragma unroll
        for (int r = 0; r < 4; r++) {
            float4 xt = *(const float4*)(X + (r0 + r) * ld + k);
            xv[r][0] = xt.x; xv[r][1] = xt.y; xv[r][2] = xt.z; xv[r][3] = xt.w;
        }
        #pragma unroll
        for (int kk = 0; kk < 4; kk++) {
            float4 w4 = *(const float4*)(Wp + (k + kk) * 64);
            u64 w01 = *reinterpret_cast<const u64*>(&w4.x);
            u64 w23 = *reinterpret_cast<const u64*>(&w4.z);
            #pragma unroll
            for (int r = 0; r < 4; r++) {
                u64 aa = dup2(xv[r][kk]);
                fma2(acc[r][0], aa, w01);
                fma2(acc[r][1], aa, w23);
            }
        }
    }
}

// 64x64 GEMM over 256 threads (16x16 thread grid, 4x4 outputs each).
// Optional second X segment (concat along K). W in [K][64] stride-64.
__device__ __forceinline__ void gemm_rows(
    const float* __restrict__ X1, int ld1, int K1c,
    const float* __restrict__ X2, int ld2, int K2c,
    const float* __restrict__ W,
    const float* __restrict__ bias,
    float scale, int act,
    float* __restrict__ Y, int ldy, int t)
{
    const int r0 = (t >> 4) << 2;
    const int c0 = (t & 15) << 2;
    u64 acc[4][2];
    #pragma unroll
    for (int r = 0; r < 4; r++) { acc[r][0] = 0ull; acc[r][1] = 0ull; }
    gemm_acc(acc, X1, ld1, K1c, W + c0, r0);
    if (X2) gemm_acc(acc, X2, ld2, K2c, W + K1c * 64 + c0, r0);
    #pragma unroll
    for (int r = 0; r < 4; r++) {
        float a0, a1, a2, a3;
        unpk(a0, a1, acc[r][0]);
        unpk(a2, a3, acc[r][1]);
        float vv[4] = {a0, a1, a2, a3};
        float4 o; float* op = (float*)&o;
        #pragma unroll
        for (int c = 0; c < 4; c++) {
            float v = vv[c] * scale + (bias ? bias[c0 + c] : 0.0f);
            if (act) v = gelu_f(v);
            op[c] = v;
        }
        *(float4*)(Y + (r0 + r) * ldy + c0) = o;
    }
}

// ================= K1: per-batch small GEMMs + attention =================
// smem layout (floats): st 64*132 | act 64*36 | se 64*68 | q 64*68 |
//                       t1 64*68 | t2 64*68 | t3 64*68 | Wbuf 10240 | sb1,sb2,sb3 64 each
#define K1_SMEM_FLOATS (8448 + 2304 + 5*4352 + 10240 + 192)

__global__ void __launch_bounds__(256) k1_kernel(
    const float* __restrict__ states, const float* __restrict__ policies,
    const float* __restrict__ actions,
    const float* __restrict__ W_se, const float* __restrict__ b_se,
    const float* __restrict__ W_k,  const float* __restrict__ b_k,
    const float* __restrict__ W_q,  const float* __restrict__ b_q,
    const float* __restrict__ W_sap,const float* __restrict__ b_sap,
    const float* __restrict__ W_av, const float* __restrict__ b_av,
    const float* __restrict__ W_ca, const float* __restrict__ b_ca,
    const float* __restrict__ g2,   const float* __restrict__ beta2,
    const float* __restrict__ W_f1,
    float* __restrict__ out_w)
{
    extern __shared__ float sm[];
    float* sh_st  = sm;                 // stride 132
    float* sh_act = sh_st + 8448;       // stride 36
    float* sh_se  = sh_act + 2304;      // stride 68
    float* sh_q   = sh_se + 4352;
    float* sh_t1  = sh_q + 4352;
    float* sh_t2  = sh_t1 + 4352;
    float* sh_t3  = sh_t2 + 4352;
    float* Wbuf   = sh_t3 + 4352;       // 10240 floats
    float* sb1 = Wbuf + 10240;
    float* sb2 = sb1 + 64;
    float* sb3 = sb2 + 64;

    const int t = threadIdx.x;
    const int b = blockIdx.x;

    // ---- se = gelu(states @ W_se + b_se)
    for (int e = t; e < Nn*OBS; e += 256)
        sh_st[(e >> 7) * 132 + (e & 127)] = states[b * (Nn*OBS) + e];
    for (int e = t; e < OBS*Dd; e += 256) Wbuf[e] = W_se[e];
    if (t < 64) sb1[t] = b_se[t];
    __syncthreads();
    gemm_rows(sh_st, 132, OBS, 0, 0, 0, Wbuf, sb1, 1.0f, 1, sh_se, 68, t);
    __syncthreads();

    // ---- k = gelu(se@W_k+b_k) -> t1 ; q = gelu(se@W_q+b_q) -> sh_q
    for (int e = t; e < 4096; e += 256) { Wbuf[e] = W_k[e]; Wbuf[4096 + e] = W_q[e]; }
    if (t < 64) { sb1[t] = b_k[t]; sb2[t] = b_q[t]; }
    __syncthreads();
    gemm_rows(sh_se, 68, 64, 0, 0, 0, Wbuf,        sb1, 1.0f, 1, sh_t1, 68, t);
    gemm_rows(sh_se, 68, 64, 0, 0, 0, Wbuf + 4096, sb2, 1.0f, 1, sh_q,  68, t);
    __syncthreads();

    // ---- transpose k -> Wbuf [d][i] (stride 64)
    for (int e = t; e < 4096; e += 256) {
        int d = e >> 6, i = e & 63;
        Wbuf[e] = sh_t1[i * 68 + d];
    }
    __syncthreads();

    // ---- scores = (q @ kT)/8 -> t3
    gemm_rows(sh_q, 68, 64, 0, 0, 0, Wbuf, (const float*)0, 0.125f, 0, sh_t3, 68, t);
    __syncthreads();

    // ---- softmax rows of t3 (4 lanes per row)
    {
        int xr = t >> 2, q = t & 3;
        float* row = sh_t3 + xr * 68 + q * 16;
        float v[16]; float m = -1e30f;
        #pragma unroll
        for (int j = 0; j < 16; j++) { v[j] = row[j]; m = fmaxf(m, v[j]); }
        m = fmaxf(m, __shfl_xor_sync(0xffffffffu, m, 1));
        m = fmaxf(m, __shfl_xor_sync(0xffffffffu, m, 2));
        float s = 0.0f;
        #pragma unroll
        for (int j = 0; j < 16; j++) { v[j] = __expf(v[j] - m); s += v[j]; }
        s += __shfl_xor_sync(0xffffffffu, s, 1);
        s += __shfl_xor_sync(0xffffffffu, s, 2);
        float inv = 1.0f / s;
        #pragma unroll
        for (int j = 0; j < 16; j++) row[j] = v[j] * inv;
    }
    __syncthreads();
    for (int e = t; e < 4096; e += 256) {
        float w = sh_t3[(e >> 6) * 68 + (e & 63)];
        out_w[b * 4096 + e] = w;
        g_w[b * 4096 + e] = w;
    }

    // ---- oape_act = gelu([states,actions] @ W_sap + b_sap) -> t1
    for (int e = t; e < Nn*ACTD; e += 256)
        sh_act[(e >> 5) * 36 + (e & 31)] = actions[b * (Nn*ACTD) + e];
    for (int e = t; e < OA*Dd; e += 256) Wbuf[e] = W_sap[e];
    if (t < 64) sb1[t] = b_sap[t];
    __syncthreads();
    gemm_rows(sh_st, 132, OBS, sh_act, 36, ACTD, Wbuf, sb1, 1.0f, 1, sh_t1, 68, t);
    __syncthreads();
    for (int e = t; e < 4096; e += 256)
        g_oape_act[b * 4096 + e] = sh_t1[(e >> 6) * 68 + (e & 63)];

    // ---- oape_pol -> t2
    for (int e = t; e < Nn*ACTD; e += 256)
        sh_act[(e >> 5) * 36 + (e & 31)] = policies[b * (Nn*ACTD) + e];
    __syncthreads();
    gemm_rows(sh_st, 132, OBS, sh_act, 36, ACTD, Wbuf, sb1, 1.0f, 1, sh_t2, 68, t);
    __syncthreads();
    for (int e = t; e < 4096; e += 256)
        g_oape_pol[b * 4096 + e] = sh_t2[(e >> 6) * 68 + (e & 63)];

    // ---- av_act = gelu(t1 @ W_av + b_av) -> Wbuf+4096 (stride 64)
    for (int e = t; e < 4096; e += 256) Wbuf[e] = W_av[e];
    if (t < 64) sb1[t] = b_av[t];
    __syncthreads();
    gemm_rows(sh_t1, 68, 64, 0, 0, 0, Wbuf, sb1, 1.0f, 1, Wbuf + 4096, 64, t);
    __syncthreads();
    // ---- av_pol -> t1 (oape_act already saved)
    gemm_rows(sh_t2, 68, 64, 0, 0, 0, Wbuf, sb1, 1.0f, 1, sh_t1, 68, t);
    __syncthreads();
    // ---- av_delta
    for (int e = t; e < 4096; e += 256) {
        int y = e >> 6, d = e & 63;
        g_av_delta[b * 4096 + e] = sh_t1[y * 68 + d] - Wbuf[4096 + e];
    }
    // ---- S_act = weight @ av_act  (weight in t3, av_act in Wbuf+4096)
    gemm_rows(sh_t3, 68, 64, 0, 0, 0, Wbuf + 4096, (const float*)0, 1.0f, 0,
              g_S + b * 4096, 64, t);
    __syncthreads();

    // ---- cae = LN(gelu(states @ W_ca + b_ca) + se; g2, beta2)
    for (int e = t; e < OBS*Dd; e += 256) Wbuf[e] = W_ca[e];
    if (t < 64) { sb1[t] = b_ca[t]; sb2[t] = g2[t]; sb3[t] = beta2[t]; }
    __syncthreads();
    gemm_rows(sh_st, 132, OBS, 0, 0, 0, Wbuf, sb1, 1.0f, 1, sh_t1, 68, t);
    __syncthreads();
    {
        int y = t >> 2, q = t & 3;
        const float* a1 = sh_t1 + y * 68 + q * 16;
        const float* a2 = sh_se + y * 68 + q * 16;
        float v[16]; float s = 0.0f, ss = 0.0f;
        #pragma unroll
        for (int j = 0; j < 16; j++) {
            float xv = a1[j] + a2[j];
            v[j] = xv; s += xv; ss = fmaf(xv, xv, ss);
        }
        s  += __shfl_xor_sync(0xffffffffu, s, 1);  s  += __shfl_xor_sync(0xffffffffu, s, 2);
        ss += __shfl_xor_sync(0xffffffffu, ss, 1); ss += __shfl_xor_sync(0xffffffffu, ss, 2);
        float mean = s * (1.0f / 64.0f);
        float var  = ss * (1.0f / 64.0f) - mean * mean;
        float inv  = rsqrtf(var + 1e-5f);
        #pragma unroll
        for (int j = 0; j < 16; j++) {
            int d = q * 16 + j;
            sh_t2[y * 68 + d] = (v[j] - mean) * inv * sb2[d] + sb3[d];
        }
    }
    __syncthreads();

    // ---- c1 = cae @ W_f1[0:64]  (no bias here; b_f1 added in K3)
    for (int e = t; e < 4096; e += 256) Wbuf[e] = W_f1[e];
    __syncthreads();
    gemm_rows(sh_t2, 68, 64, 0, 0, 0, Wbuf, (const float*)0, 1.0f, 0,
              g_c1 + b * 4096, 64, t);
}

// ================= K3: per-(b,x) 64x64 tile: nf build + LN + 2 layers + head =================
// smem: nf 64*68 | h 64*68 | W1 4096 | W2 4096 | sv 512
#define K3_SMEM_FLOATS (2*4352 + 2*4096 + 512)

__global__ void __launch_bounds__(256) k3_kernel(
    const float* __restrict__ W_f1, const float* __restrict__ b_f1,
    const float* __restrict__ W_f2, const float* __restrict__ b_f2,
    const float* __restrict__ W_f3, const float* __restrict__ b_f3,
    const float* __restrict__ g1,   const float* __restrict__ beta1,
    float* __restrict__ out_val)
{
    extern __shared__ float sm[];
    float* sh_nf = sm;               // stride 68
    float* sh_h  = sm + 4352;        // stride 68
    float* sW1   = sm + 8704;        // [64][64]
    float* sW2   = sW1 + 4096;
    float* sv    = sW2 + 4096;       // W3 |b1 |b2 |S |c1 |w |g1 |beta1  (8 x 64)

    const int t = threadIdx.x;
    const int bid = blockIdx.x;      // b*64 + x
    const int b = bid >> 6;
    const int x = bid & 63;

    for (int e = t; e < 4096; e += 256) {
        sW1[e] = W_f1[4096 + e];     // bottom half rows 64..127
        sW2[e] = W_f2[e];
    }
    if (t < 64) {
        sv[t]        = W_f3[t];
        sv[64 + t]   = b_f1[t];
        sv[128 + t]  = b_f2[t];
        sv[192 + t]  = g_S[bid * 64 + t];
        sv[256 + t]  = g_c1[bid * 64 + t];
        sv[320 + t]  = g_w[bid * 64 + t];
        sv[384 + t]  = g1[t];
        sv[448 + t]  = beta1[t];
    }
    __syncthreads();

    // build nf tile: nf[y][d] = oape_sel + S_act[d] + w[y]*av_delta[y][d]
    {
        const float* oa = g_oape_act + b * 4096;
        const float* op = g_oape_pol + b * 4096;
        const float* dv = g_av_delta + b * 4096;
        for (int e = t; e < 1024; e += 256) {
            int yy = e >> 4, d4 = (e & 15) << 2;
            const float* basep = (yy == x) ? op : oa;
            float4 ba  = *(const float4*)(basep + yy * 64 + d4);
            float4 dvv = *(const float4*)(dv + yy * 64 + d4);
            float wv = sv[320 + yy];
            float4 o;
            o.x = ba.x + sv[192 + d4 + 0] + wv * dvv.x;
            o.y = ba.y + sv[192 + d4 + 1] + wv * dvv.y;
            o.z = ba.z + sv[192 + d4 + 2] + wv * dvv.z;
            o.w = ba.w + sv[192 + d4 + 3] + wv * dvv.w;
            *(float4*)(sh_nf + yy * 68 + d4) = o;
        }
    }
    __syncthreads();

    // LayerNorm rows (g1, beta1), in place
    {
        int yy = t >> 2, q = t & 3;
        float* r = sh_nf + yy * 68 + q * 16;
        float v[16]; float s = 0.0f, ss = 0.0f;
        #pragma unroll
        for (int j = 0; j < 16; j++) {
            float xv = r[j]; v[j] = xv; s += xv; ss = fmaf(xv, xv, ss);
        }
        s  += __shfl_xor_sync(0xffffffffu, s, 1);  s  += __shfl_xor_sync(0xffffffffu, s, 2);
        ss += __shfl_xor_sync(0xffffffffu, ss, 1); ss += __shfl_xor_sync(0xffffffffu, ss, 2);
        float mean = s * (1.0f / 64.0f);
        float var  = ss * (1.0f / 64.0f) - mean * mean;
        float inv  = rsqrtf(var + 1e-5f);
        #pragma unroll
        for (int j = 0; j < 16; j++) {
            int d = q * 16 + j;
            r[j] = (v[j] - mean) * inv * sv[384 + d] + sv[448 + d];
        }
    }
    __syncthreads();

    const int r0 = (t >> 4) << 2;
    const int c0 = (t & 15) << 2;

    // Layer 1: h = gelu(c1 + nf @ W1bot + b1)
    {
        u64 acc[4][2];
        #pragma unroll
        for (int r = 0; r < 4; r++) { acc[r][0] = 0ull; acc[r][1] = 0ull; }
        gemm_acc(acc, sh_nf, 68, 64, sW1 + c0, r0);
        #pragma unroll
        for (int r = 0; r < 4; r++) {
            float a0, a1, a2, a3;
            unpk(a0, a1, acc[r][0]);
            unpk(a2, a3, acc[r][1]);
            float vv[4] = {a0, a1, a2, a3};
            float4 o; float* op = (float*)&o;
            #pragma unroll
            for (int c = 0; c < 4; c++)
                op[c] = gelu_f(vv[c] + sv[256 + c0 + c] + sv[64 + c0 + c]);
            *(float4*)(sh_h + (r0 + r) * 68 + c0) = o;
        }
    }
    __syncthreads();

    // Layer 2: h2 = gelu(h @ W2 + b2) -> reuse sh_nf
    {
        u64 acc[4][2];
        #pragma unroll
        for (int r = 0; r < 4; r++) { acc[r][0] = 0ull; acc[r][1] = 0ull; }
        gemm_acc(acc, sh_h, 68, 64, sW2 + c0, r0);
        #pragma unroll
        for (int r = 0; r < 4; r++) {
            float a0, a1, a2, a3;
            unpk(a0, a1, acc[r][0]);
            unpk(a2, a3, acc[r][1]);
            float vv[4] = {a0, a1, a2, a3};
            float4 o; float* op = (float*)&o;
            #pragma unroll
            for (int c = 0; c < 4; c++)
                op[c] = gelu_f(vv[c] + sv[128 + c0 + c]);
            *(float4*)(sh_nf + (r0 + r) * 68 + c0) = o;
        }
    }
    __syncthreads();

    // Head: value = h2 . W3 + b3
    {
        int yy = t >> 2, q = t & 3;
        const float* r = sh_nf + yy * 68 + q * 16;
        float s = 0.0f;
        #pragma unroll
        for (int j = 0; j < 16; j++) s = fmaf(r[j], sv[q * 16 + j], s);
        s += __shfl_xor_sync(0xffffffffu, s, 1);
        s += __shfl_xor_sync(0xffffffffu, s, 2);
        if (q == 0) out_val[bid * 64 + yy] = s + b_f3[0];
    }
}

extern "C" void kernel_launch(void* const* d_in, const int* in_sizes, int n_in,
                              void* d_out, int out_size)
{
    const float* states   = (const float*)d_in[0];
    const float* policies = (const float*)d_in[1];
    const float* actions  = (const float*)d_in[2];
    const float* W_se = (const float*)d_in[3];  const float* b_se = (const float*)d_in[4];
    const float* W_k  = (const float*)d_in[5];  const float* b_k  = (const float*)d_in[6];
    const float* W_q  = (const float*)d_in[7];  const float* b_q  = (const float*)d_in[8];
    const float* W_sap= (const float*)d_in[9];  const float* b_sap= (const float*)d_in[10];
    const float* W_av = (const float*)d_in[11]; const float* b_av = (const float*)d_in[12];
    const float* g1   = (const float*)d_in[13]; const float* beta1= (const float*)d_in[14];
    const float* W_ca = (const float*)d_in[15]; const float* b_ca = (const float*)d_in[16];
    const float* g2   = (const float*)d_in[17]; const float* beta2= (const float*)d_in[18];
    const float* W_f1 = (const float*)d_in[19]; const float* b_f1 = (const float*)d_in[20];
    const float* W_f2 = (const float*)d_in[21]; const float* b_f2 = (const float*)d_in[22];
    const float* W_f3 = (const float*)d_in[23]; const float* b_f3 = (const float*)d_in[24];

    float* out = (float*)d_out;
    float* out_val = out;                         // [B,N,N,1] = 524288
    float* out_w   = out + Bsz * Nn * Nn;         // [B,N,N]   = 524288

    size_t k1_smem = (size_t)K1_SMEM_FLOATS * sizeof(float);
    size_t k3_smem = (size_t)K3_SMEM_FLOATS * sizeof(float);
    cudaFuncSetAttribute(k1_kernel, cudaFuncAttributeMaxDynamicSharedMemorySize, (int)k1_smem);
    cudaFuncSetAttribute(k3_kernel, cudaFuncAttributeMaxDynamicSharedMemorySize, (int)k3_smem);

    k1_kernel<<<Bsz, 256, k1_smem>>>(
        states, policies, actions,
        W_se, b_se, W_k, b_k, W_q, b_q, W_sap, b_sap, W_av, b_av,
        W_ca, b_ca, g2, beta2, W_f1, out_w);

    k3_kernel<<<Bsz * Nn, 256, k3_smem>>>(
        W_f1, b_f1, W_f2, b_f2, W_f3, b_f3, g1, beta1, out_val);
}

// round 12
// speedup vs baseline: 1.0581x; 1.0581x over previous
#include <cuda_runtime.h>
#include <math.h>

#define Bsz 128
#define Nn  64
#define OBS 128
#define ACTD 32
#define OA  160
#define Dd  64

typedef unsigned long long u64;

// -------- scratch (no runtime alloc allowed) --------
__device__ float g_oape_act[Bsz*Nn*Dd];
__device__ float g_oape_pol[Bsz*Nn*Dd];
__device__ float g_av_delta[Bsz*Nn*Dd];
__device__ float g_S[Bsz*Nn*Dd];
__device__ float g_c1[Bsz*Nn*Dd];
__device__ float g_w[Bsz*Nn*Nn];

// Branch-free erf (Abramowitz-Stegun 7.1.26, max abs err 1.5e-7) -> exact-enough GELU.
__device__ __forceinline__ float gelu_f(float x) {
    float z = x * 0.70710678118654752440f;
    float a = fabsf(z);
    float t = __fdividef(1.0f, fmaf(0.3275911f, a, 1.0f));
    float p = fmaf(t, 1.061405429f, -1.453152027f);
    p = fmaf(t, p, 1.421413741f);
    p = fmaf(t, p, -0.284496736f);
    p = fmaf(t, p, 0.254829592f);
    p = p * t;
    float e = 1.0f - p * __expf(-a * a);
    float erfv = copysignf(e, z);
    return 0.5f * x * (1.0f + erfv);
}

// ---- packed f32x2 helpers (sm_103a; FFMA2 only reachable via PTX) ----
__device__ __forceinline__ u64 dup2(float v) {
    u64 r; asm("mov.b64 %0, {%1, %1};" : "=l"(r) : "f"(v)); return r;
}
__device__ __forceinline__ void fma2(u64 &d, u64 a, u64 b) {
    asm("fma.rn.f32x2 %0, %1, %2, %3;" : "=l"(d) : "l"(a), "l"(b), "l"(d));
}
__device__ __forceinline__ void unpk(float &lo, float &hi, u64 v) {
    asm("mov.b64 {%0, %1}, %2;" : "=f"(lo), "=f"(hi) : "l"(v));
}

// ===================== K1 helpers (256 threads, 4x4 microtile) =====================
__device__ __forceinline__ void gemm_acc(u64 acc[4][2],
    const float* __restrict__ X, int ld, int Kc,
    const float* __restrict__ Wp, int r0)
{
    #pragma unroll 4
    for (int k = 0; k < Kc; k += 4) {
        float xv[4][4];
        #pragma unroll
        for (int r = 0; r < 4; r++) {
            float4 xt = *(const float4*)(X + (r0 + r) * ld + k);
            xv[r][0] = xt.x; xv[r][1] = xt.y; xv[r][2] = xt.z; xv[r][3] = xt.w;
        }
        #pragma unroll
        for (int kk = 0; kk < 4; kk++) {
            float4 w4 = *(const float4*)(Wp + (k + kk) * 64);
            u64 w01 = *reinterpret_cast<const u64*>(&w4.x);
            u64 w23 = *reinterpret_cast<const u64*>(&w4.z);
            #pragma unroll
            for (int r = 0; r < 4; r++) {
                u64 aa = dup2(xv[r][kk]);
                fma2(acc[r][0], aa, w01);
                fma2(acc[r][1], aa, w23);
            }
        }
    }
}

__device__ __forceinline__ void gemm_rows(
    const float* __restrict__ X1, int ld1, int K1c,
    const float* __restrict__ X2, int ld2, int K2c,
    const float* __restrict__ W,
    const float* __restrict__ bias,
    float scale, int act,
    float* __restrict__ Y, int ldy, int t)
{
    const int r0 = (t >> 4) << 2;
    const int c0 = (t & 15) << 2;
    u64 acc[4][2];
    #pragma unroll
    for (int r = 0; r < 4; r++) { acc[r][0] = 0ull; acc[r][1] = 0ull; }
    gemm_acc(acc, X1, ld1, K1c, W + c0, r0);
    if (X2) gemm_acc(acc, X2, ld2, K2c, W + K1c * 64 + c0, r0);
    #pragma unroll
    for (int r = 0; r < 4; r++) {
        float a0, a1, a2, a3;
        unpk(a0, a1, acc[r][0]);
        unpk(a2, a3, acc[r][1]);
        float vv[4] = {a0, a1, a2, a3};
        float4 o; float* op = (float*)&o;
        #pragma unroll
        for (int c = 0; c < 4; c++) {
            float v = vv[c] * scale + (bias ? bias[c0 + c] : 0.0f);
            if (act) v = gelu_f(v);
            op[c] = v;
        }
        *(float4*)(Y + (r0 + r) * ldy + c0) = o;
    }
}

// ================= K1: per-batch small GEMMs + attention (unchanged) =================
#define K1_SMEM_FLOATS (8448 + 2304 + 5*4352 + 10240 + 192)

__global__ void __launch_bounds__(256) k1_kernel(
    const float* __restrict__ states, const float* __restrict__ policies,
    const float* __restrict__ actions,
    const float* __restrict__ W_se, const float* __restrict__ b_se,
    const float* __restrict__ W_k,  const float* __restrict__ b_k,
    const float* __restrict__ W_q,  const float* __restrict__ b_q,
    const float* __restrict__ W_sap,const float* __restrict__ b_sap,
    const float* __restrict__ W_av, const float* __restrict__ b_av,
    const float* __restrict__ W_ca, const float* __restrict__ b_ca,
    const float* __restrict__ g2,   const float* __restrict__ beta2,
    const float* __restrict__ W_f1,
    float* __restrict__ out_w)
{
    extern __shared__ float sm[];
    float* sh_st  = sm;                 // stride 132
    float* sh_act = sh_st + 8448;       // stride 36
    float* sh_se  = sh_act + 2304;      // stride 68
    float* sh_q   = sh_se + 4352;
    float* sh_t1  = sh_q + 4352;
    float* sh_t2  = sh_t1 + 4352;
    float* sh_t3  = sh_t2 + 4352;
    float* Wbuf   = sh_t3 + 4352;       // 10240 floats
    float* sb1 = Wbuf + 10240;
    float* sb2 = sb1 + 64;
    float* sb3 = sb2 + 64;

    const int t = threadIdx.x;
    const int b = blockIdx.x;

    for (int e = t; e < Nn*OBS; e += 256)
        sh_st[(e >> 7) * 132 + (e & 127)] = states[b * (Nn*OBS) + e];
    for (int e = t; e < OBS*Dd; e += 256) Wbuf[e] = W_se[e];
    if (t < 64) sb1[t] = b_se[t];
    __syncthreads();
    gemm_rows(sh_st, 132, OBS, 0, 0, 0, Wbuf, sb1, 1.0f, 1, sh_se, 68, t);
    __syncthreads();

    for (int e = t; e < 4096; e += 256) { Wbuf[e] = W_k[e]; Wbuf[4096 + e] = W_q[e]; }
    if (t < 64) { sb1[t] = b_k[t]; sb2[t] = b_q[t]; }
    __syncthreads();
    gemm_rows(sh_se, 68, 64, 0, 0, 0, Wbuf,        sb1, 1.0f, 1, sh_t1, 68, t);
    gemm_rows(sh_se, 68, 64, 0, 0, 0, Wbuf + 4096, sb2, 1.0f, 1, sh_q,  68, t);
    __syncthreads();

    for (int e = t; e < 4096; e += 256) {
        int d = e >> 6, i = e & 63;
        Wbuf[e] = sh_t1[i * 68 + d];
    }
    __syncthreads();

    gemm_rows(sh_q, 68, 64, 0, 0, 0, Wbuf, (const float*)0, 0.125f, 0, sh_t3, 68, t);
    __syncthreads();

    {
        int xr = t >> 2, q = t & 3;
        float* row = sh_t3 + xr * 68 + q * 16;
        float v[16]; float m = -1e30f;
        #pragma unroll
        for (int j = 0; j < 16; j++) { v[j] = row[j]; m = fmaxf(m, v[j]); }
        m = fmaxf(m, __shfl_xor_sync(0xffffffffu, m, 1));
        m = fmaxf(m, __shfl_xor_sync(0xffffffffu, m, 2));
        float s = 0.0f;
        #pragma unroll
        for (int j = 0; j < 16; j++) { v[j] = __expf(v[j] - m); s += v[j]; }
        s += __shfl_xor_sync(0xffffffffu, s, 1);
        s += __shfl_xor_sync(0xffffffffu, s, 2);
        float inv = 1.0f / s;
        #pragma unroll
        for (int j = 0; j < 16; j++) row[j] = v[j] * inv;
    }
    __syncthreads();
    for (int e = t; e < 4096; e += 256) {
        float w = sh_t3[(e >> 6) * 68 + (e & 63)];
        out_w[b * 4096 + e] = w;
        g_w[b * 4096 + e] = w;
    }

    for (int e = t; e < Nn*ACTD; e += 256)
        sh_act[(e >> 5) * 36 + (e & 31)] = actions[b * (Nn*ACTD) + e];
    for (int e = t; e < OA*Dd; e += 256) Wbuf[e] = W_sap[e];
    if (t < 64) sb1[t] = b_sap[t];
    __syncthreads();
    gemm_rows(sh_st, 132, OBS, sh_act, 36, ACTD, Wbuf, sb1, 1.0f, 1, sh_t1, 68, t);
    __syncthreads();
    for (int e = t; e < 4096; e += 256)
        g_oape_act[b * 4096 + e] = sh_t1[(e >> 6) * 68 + (e & 63)];

    for (int e = t; e < Nn*ACTD; e += 256)
        sh_act[(e >> 5) * 36 + (e & 31)] = policies[b * (Nn*ACTD) + e];
    __syncthreads();
    gemm_rows(sh_st, 132, OBS, sh_act, 36, ACTD, Wbuf, sb1, 1.0f, 1, sh_t2, 68, t);
    __syncthreads();
    for (int e = t; e < 4096; e += 256)
        g_oape_pol[b * 4096 + e] = sh_t2[(e >> 6) * 68 + (e & 63)];

    for (int e = t; e < 4096; e += 256) Wbuf[e] = W_av[e];
    if (t < 64) sb1[t] = b_av[t];
    __syncthreads();
    gemm_rows(sh_t1, 68, 64, 0, 0, 0, Wbuf, sb1, 1.0f, 1, Wbuf + 4096, 64, t);
    __syncthreads();
    gemm_rows(sh_t2, 68, 64, 0, 0, 0, Wbuf, sb1, 1.0f, 1, sh_t1, 68, t);
    __syncthreads();
    for (int e = t; e < 4096; e += 256) {
        int y = e >> 6, d = e & 63;
        g_av_delta[b * 4096 + e] = sh_t1[y * 68 + d] - Wbuf[4096 + e];
    }
    gemm_rows(sh_t3, 68, 64, 0, 0, 0, Wbuf + 4096, (const float*)0, 1.0f, 0,
              g_S + b * 4096, 64, t);
    __syncthreads();

    for (int e = t; e < OBS*Dd; e += 256) Wbuf[e] = W_ca[e];
    if (t < 64) { sb1[t] = b_ca[t]; sb2[t] = g2[t]; sb3[t] = beta2[t]; }
    __syncthreads();
    gemm_rows(sh_st, 132, OBS, 0, 0, 0, Wbuf, sb1, 1.0f, 1, sh_t1, 68, t);
    __syncthreads();
    {
        int y = t >> 2, q = t & 3;
        const float* a1 = sh_t1 + y * 68 + q * 16;
        const float* a2 = sh_se + y * 68 + q * 16;
        float v[16]; float s = 0.0f, ss = 0.0f;
        #pragma unroll
        for (int j = 0; j < 16; j++) {
            float xv = a1[j] + a2[j];
            v[j] = xv; s += xv; ss = fmaf(xv, xv, ss);
        }
        s  += __shfl_xor_sync(0xffffffffu, s, 1);  s  += __shfl_xor_sync(0xffffffffu, s, 2);
        ss += __shfl_xor_sync(0xffffffffu, ss, 1); ss += __shfl_xor_sync(0xffffffffu, ss, 2);
        float mean = s * (1.0f / 64.0f);
        float var  = ss * (1.0f / 64.0f) - mean * mean;
        float inv  = rsqrtf(var + 1e-5f);
        #pragma unroll
        for (int j = 0; j < 16; j++) {
            int d = q * 16 + j;
            sh_t2[y * 68 + d] = (v[j] - mean) * inv * sb2[d] + sb3[d];
        }
    }
    __syncthreads();

    for (int e = t; e < 4096; e += 256) Wbuf[e] = W_f1[e];
    __syncthreads();
    gemm_rows(sh_t2, 68, 64, 0, 0, 0, Wbuf, (const float*)0, 1.0f, 0,
              g_c1 + b * 4096, 64, t);
}

// ================= K3: per-(b,x) tile, 128 threads, 4-row x 8-col microtile =================
// smem: nf 64*68 | h 64*68 | W1 4096 | W2 4096 | sv 512  = 17408 floats (69.6KB)
#define K3_SMEM_FLOATS (2*4352 + 2*4096 + 512)

// One FC layer: Y[64][68] = act(addv + X[64][68] @ W[64][64]).
// Thread t: rows r0=(t>>3)*4 .. +3; cols {c0..c0+3, c0+32..c0+35}, c0=(t&7)*4.
__device__ __forceinline__ void fc_layer_128(
    const float* __restrict__ X,      // stride 68
    const float* __restrict__ Wm,     // [64][64]
    const float* __restrict__ addv,   // 64 per-col adds (in smem)
    float* __restrict__ Y, int t)
{
    const int r0 = (t >> 3) << 2;
    const int c0 = (t & 7) << 2;
    u64 acc[4][4];
    #pragma unroll
    for (int r = 0; r < 4; r++)
        #pragma unroll
        for (int c = 0; c < 4; c++) acc[r][c] = 0ull;

    const float* xb = X + r0 * 68;
    #pragma unroll 4
    for (int k = 0; k < 64; k += 4) {
        float xv[4][4];
        #pragma unroll
        for (int r = 0; r < 4; r++) {
            float4 xt = *(const float4*)(xb + r * 68 + k);
            xv[r][0] = xt.x; xv[r][1] = xt.y; xv[r][2] = xt.z; xv[r][3] = xt.w;
        }
        #pragma unroll
        for (int kk = 0; kk < 4; kk++) {
            const float* wr = Wm + (k + kk) * 64;
            float4 wa = *(const float4*)(wr + c0);
            float4 wb = *(const float4*)(wr + c0 + 32);
            u64 wa01 = *reinterpret_cast<const u64*>(&wa.x);
            u64 wa23 = *reinterpret_cast<const u64*>(&wa.z);
            u64 wb01 = *reinterpret_cast<const u64*>(&wb.x);
            u64 wb23 = *reinterpret_cast<const u64*>(&wb.z);
            #pragma unroll
            for (int r = 0; r < 4; r++) {
                u64 aa = dup2(xv[r][kk]);
                fma2(acc[r][0], aa, wa01);
                fma2(acc[r][1], aa, wa23);
                fma2(acc[r][2], aa, wb01);
                fma2(acc[r][3], aa, wb23);
            }
        }
    }
    #pragma unroll
    for (int r = 0; r < 4; r++) {
        float v[8];
        unpk(v[0], v[1], acc[r][0]);
        unpk(v[2], v[3], acc[r][1]);
        unpk(v[4], v[5], acc[r][2]);
        unpk(v[6], v[7], acc[r][3]);
        float4 oa, ob;
        float* pa = (float*)&oa; float* pb = (float*)&ob;
        #pragma unroll
        for (int c = 0; c < 4; c++) {
            pa[c] = gelu_f(v[c]     + addv[c0 + c]);
            pb[c] = gelu_f(v[4 + c] + addv[c0 + 32 + c]);
        }
        *(float4*)(Y + (r0 + r) * 68 + c0)      = oa;
        *(float4*)(Y + (r0 + r) * 68 + c0 + 32) = ob;
    }
}

__global__ void __launch_bounds__(128) k3_kernel(
    const float* __restrict__ W_f1, const float* __restrict__ b_f1,
    const float* __restrict__ W_f2, const float* __restrict__ b_f2,
    const float* __restrict__ W_f3, const float* __restrict__ b_f3,
    const float* __restrict__ g1,   const float* __restrict__ beta1,
    float* __restrict__ out_val)
{
    extern __shared__ float sm[];
    float* sh_nf = sm;               // stride 68
    float* sh_h  = sm + 4352;        // stride 68
    float* sW1   = sm + 8704;        // [64][64]
    float* sW2   = sW1 + 4096;
    float* sv    = sW2 + 4096;       // W3 |add1(c1+b1) |b2 |S |w |g1 |beta1 | spare

    const int t = threadIdx.x;
    const int bid = blockIdx.x;      // b*64 + x
    const int b = bid >> 6;
    const int x = bid & 63;

    // stage weights (float4 loads; W_f1 bottom half rows 64..127)
    {
        const float4* w1p = (const float4*)(W_f1 + 4096);
        const float4* w2p = (const float4*)W_f2;
        float4* s1 = (float4*)sW1;
        float4* s2 = (float4*)sW2;
        for (int e = t; e < 1024; e += 128) { s1[e] = w1p[e]; s2[e] = w2p[e]; }
    }
    if (t < 64) {
        sv[t]        = W_f3[t];
        sv[64 + t]   = g_c1[bid * 64 + t] + b_f1[t];   // fused add for layer 1
        sv[128 + t]  = b_f2[t];
        sv[192 + t]  = g_S[bid * 64 + t];
        sv[256 + t]  = g_w[bid * 64 + t];
        sv[320 + t]  = g1[t];
        sv[384 + t]  = beta1[t];
    }
    __syncthreads();

    // build nf tile: nf[y][d] = oape_sel + S_act[d] + w[y]*av_delta[y][d]
    {
        const float* oa = g_oape_act + b * 4096;
        const float* op = g_oape_pol + b * 4096;
        const float* dv = g_av_delta + b * 4096;
        for (int e = t; e < 1024; e += 128) {
            int yy = e >> 4, d4 = (e & 15) << 2;
            const float* basep = (yy == x) ? op : oa;
            float4 ba  = *(const float4*)(basep + yy * 64 + d4);
            float4 dvv = *(const float4*)(dv + yy * 64 + d4);
            float wv = sv[256 + yy];
            float4 o;
            o.x = ba.x + sv[192 + d4 + 0] + wv * dvv.x;
            o.y = ba.y + sv[192 + d4 + 1] + wv * dvv.y;
            o.z = ba.z + sv[192 + d4 + 2] + wv * dvv.z;
            o.w = ba.w + sv[192 + d4 + 3] + wv * dvv.w;
            *(float4*)(sh_nf + yy * 68 + d4) = o;
        }
    }
    __syncthreads();

    // LayerNorm rows (g1, beta1), in place; 2 threads per row, 32 values each.
    {
        int yy = t >> 1, half = t & 1;
        float* r = sh_nf + yy * 68 + half * 32;
        float v[32]; float s = 0.0f, ss = 0.0f;
        #pragma unroll
        for (int j = 0; j < 32; j++) {
            float xv = r[j]; v[j] = xv; s += xv; ss = fmaf(xv, xv, ss);
        }
        s  += __shfl_xor_sync(0xffffffffu, s, 1);
        ss += __shfl_xor_sync(0xffffffffu, ss, 1);
        float mean = s * (1.0f / 64.0f);
        float var  = ss * (1.0f / 64.0f) - mean * mean;
        float inv  = rsqrtf(var + 1e-5f);
        #pragma unroll
        for (int j = 0; j < 32; j++) {
            int d = half * 32 + j;
            r[j] = (v[j] - mean) * inv * sv[320 + d] + sv[384 + d];
        }
    }
    __syncthreads();

    // Layer 1: h = gelu((c1 + b1) + nf @ W1bot)
    fc_layer_128(sh_nf, sW1, sv + 64, sh_h, t);
    __syncthreads();

    // Layer 2: h2 = gelu(b2 + h @ W2) -> reuse sh_nf
    fc_layer_128(sh_h, sW2, sv + 128, sh_nf, t);
    __syncthreads();

    // Head: value = h2 . W3 + b3 ; 2 threads per row
    {
        int yy = t >> 1, half = t & 1;
        const float* r = sh_nf + yy * 68 + half * 32;
        const float* w3 = sv + half * 32;
        float s = 0.0f;
        #pragma unroll
        for (int j = 0; j < 32; j++) s = fmaf(r[j], w3[j], s);
        s += __shfl_xor_sync(0xffffffffu, s, 1);
        if (half == 0) out_val[bid * 64 + yy] = s + b_f3[0];
    }
}

extern "C" void kernel_launch(void* const* d_in, const int* in_sizes, int n_in,
                              void* d_out, int out_size)
{
    const float* states   = (const float*)d_in[0];
    const float* policies = (const float*)d_in[1];
    const float* actions  = (const float*)d_in[2];
    const float* W_se = (const float*)d_in[3];  const float* b_se = (const float*)d_in[4];
    const float* W_k  = (const float*)d_in[5];  const float* b_k  = (const float*)d_in[6];
    const float* W_q  = (const float*)d_in[7];  const float* b_q  = (const float*)d_in[8];
    const float* W_sap= (const float*)d_in[9];  const float* b_sap= (const float*)d_in[10];
    const float* W_av = (const float*)d_in[11]; const float* b_av = (const float*)d_in[12];
    const float* g1   = (const float*)d_in[13]; const float* beta1= (const float*)d_in[14];
    const float* W_ca = (const float*)d_in[15]; const float* b_ca = (const float*)d_in[16];
    const float* g2   = (const float*)d_in[17]; const float* beta2= (const float*)d_in[18];
    const float* W_f1 = (const float*)d_in[19]; const float* b_f1 = (const float*)d_in[20];
    const float* W_f2 = (const float*)d_in[21]; const float* b_f2 = (const float*)d_in[22];
    const float* W_f3 = (const float*)d_in[23]; const float* b_f3 = (const float*)d_in[24];

    float* out = (float*)d_out;
    float* out_val = out;                         // [B,N,N,1] = 524288
    float* out_w   = out + Bsz * Nn * Nn;         // [B,N,N]   = 524288

    size_t k1_smem = (size_t)K1_SMEM_FLOATS * sizeof(float);
    size_t k3_smem = (size_t)K3_SMEM_FLOATS * sizeof(float);
    cudaFuncSetAttribute(k1_kernel, cudaFuncAttributeMaxDynamicSharedMemorySize, (int)k1_smem);
    cudaFuncSetAttribute(k3_kernel, cudaFuncAttributeMaxDynamicSharedMemorySize, (int)k3_smem);

    k1_kernel<<<Bsz, 256, k1_smem>>>(
        states, policies, actions,
        W_se, b_se, W_k, b_k, W_q, b_q, W_sap, b_sap, W_av, b_av,
        W_ca, b_ca, g2, beta2, W_f1, out_w);

    k3_kernel<<<Bsz * Nn, 128, k3_smem>>>(
        W_f1, b_f1, W_f2, b_f2, W_f3, b_f3, g1, beta1, out_val);
}